// round 6
// baseline (speedup 1.0000x reference)
#include <cuda_runtime.h>

// Soft decision tree path probabilities — one warp per row, barrier/smem-free.
// DEPTH=8, N_NODES=255, N_LEAVES=256, BATCH=512.
//
// Grid=512 (one 32-thread CTA per batch row). Thread u owns the depth-5
// subtree over leaves 8u..8u+7. Its 12 x-loads are index-computable and
// issued together:
//   top path d=0..4 : node = (2^d-1) + (u >> (5-d))
//   depth-5         : 31 + u
//   depth-6         : 63+2u, 64+2u
//   depth-7         : 127+4u .. 130+4u
// Prefix product before the depth-d factor IS node_d's path prob: top nodes
// written by the leftmost thread of each subtree; nodes from depth 5 down
// written unconditionally by their owner. Child 2i+1 takes factor x[i],
// child 2i+2 takes 1-x[i].
//
// Output: [ leaf_probs (512 x 256) ; node_probs (512 x 255) ] row-major.

__global__ __launch_bounds__(32) void tree_path_kernel(
    const float* __restrict__ x,   // (BATCH, 255)
    float* __restrict__ out,
    int batch)
{
    const unsigned u = threadIdx.x;          // 0..31
    const unsigned b = blockIdx.x;

    const float* __restrict__ xr = x + b * 255u;
    float* __restrict__ on = out + (unsigned)batch * 256u + b * 255u;

    // ---- issue all 12 independent loads up front ----
    float xt[5];
#pragma unroll
    for (int d = 0; d < 5; ++d) {
        const unsigned node = ((1u << d) - 1u) + (u >> (5 - d));
        xt[d] = __ldg(xr + node);
    }
    const float x5  = __ldg(xr + 31u + u);
    const float x6a = __ldg(xr + 63u + 2u * u);
    const float x6b = __ldg(xr + 64u + 2u * u);
    const float x7a = __ldg(xr + 127u + 4u * u);
    const float x7b = __ldg(xr + 128u + 4u * u);
    const float x7c = __ldg(xr + 129u + 4u * u);
    const float x7d = __ldg(xr + 130u + 4u * u);

    // ---- top path prefix product, emitting top node probs ----
    float p = 1.0f;
#pragma unroll
    for (int d = 0; d < 5; ++d) {
        const unsigned node = ((1u << d) - 1u) + (u >> (5 - d));
        if ((u & ((1u << (5 - d)) - 1u)) == 0u) {
            on[node] = p;                    // path prob of node at depth d
        }
        p *= ((u >> (4 - d)) & 1u) ? (1.0f - xt[d]) : xt[d];
    }

    // ---- exclusively-owned nodes ----
    on[31u + u] = p;                         // depth 5
    const float p6a = p * x5;                // node 63+2u
    const float p6b = p * (1.0f - x5);       // node 64+2u
    on[63u + 2u * u] = p6a;
    on[64u + 2u * u] = p6b;

    const float p7a = p6a * x6a;             // node 127+4u
    const float p7b = p6a * (1.0f - x6a);    // node 128+4u
    const float p7c = p6b * x6b;             // node 129+4u
    const float p7d = p6b * (1.0f - x6b);    // node 130+4u
    on[127u + 4u * u] = p7a;
    on[128u + 4u * u] = p7b;
    on[129u + 4u * u] = p7c;
    on[130u + 4u * u] = p7d;

    // ---- leaves 8u..8u+7 (two aligned float4 stores) ----
    float4 l0, l1;
    l0.x = p7a * x7a;  l0.y = p7a * (1.0f - x7a);
    l0.z = p7b * x7b;  l0.w = p7b * (1.0f - x7b);
    l1.x = p7c * x7c;  l1.y = p7c * (1.0f - x7c);
    l1.z = p7d * x7d;  l1.w = p7d * (1.0f - x7d);
    float4* lp = reinterpret_cast<float4*>(out + b * 256u + 8u * u);
    lp[0] = l0;
    lp[1] = l1;
}

extern "C" void kernel_launch(void* const* d_in, const int* in_sizes, int n_in,
                              void* d_out, int out_size) {
    const float* x = (const float*)d_in[0];  // (BATCH, 255) float32
    float* out = (float*)d_out;
    const int batch = in_sizes[0] / 255;     // 512
    tree_path_kernel<<<batch, 32>>>(x, out, batch);
}

// round 8
// speedup vs baseline: 1.0337x; 1.0337x over previous
#include <cuda_runtime.h>

// Soft decision tree path probabilities — barrier-free, smem-free.
// DEPTH=8, N_NODES=255, N_LEAVES=256, BATCH=512.
// R5 shape (best measured): one row per 64-thread CTA, grid=512.
//
// Thread u owns the depth-6 subtree over leaves 4u..4u+3. Its 9 x-loads are
// index-computable and issued together:
//   top path d=0..5 : node = (2^d-1) + (u >> (6-d))
//   depth-6         : 63 + u
//   depth-7         : 127+2u, 128+2u
// Prefix product before the depth-d factor IS node_d's path prob: top nodes
// written by the leftmost thread of each subtree; nodes 63+u, 127+2u, 128+2u
// written unconditionally by their owner. Child 2i+1 takes factor x[i],
// child 2i+2 takes 1-x[i]. (1-x)*p computed as fmaf(-x, p, p): one FFMA
// instead of FADD+FMUL; rounding differs by ~1 ulp, far inside the 1e-3
// tolerance, and x,p in [0,1] keeps it stable.
//
// Output: [ leaf_probs (512 x 256) ; node_probs (512 x 255) ] row-major.

__device__ __forceinline__ float one_minus_mul(float xv, float p) {
    // (1 - xv) * p  ==  p - xv*p  (one FFMA)
    return fmaf(-xv, p, p);
}

__global__ __launch_bounds__(64) void tree_path_kernel(
    const float* __restrict__ x,   // (BATCH, 255)
    float* __restrict__ out,
    int batch)
{
    const unsigned u = threadIdx.x;          // 0..63
    const unsigned b = blockIdx.x;

    const float* __restrict__ xr = x + b * 255u;
    float* __restrict__ on = out + (unsigned)batch * 256u + b * 255u;

    // ---- issue all 9 independent loads up front ----
    float xt[6];
#pragma unroll
    for (int d = 0; d < 6; ++d) {
        const unsigned node = ((1u << d) - 1u) + (u >> (6 - d));
        xt[d] = __ldg(xr + node);
    }
    const unsigned u2 = 2u * u;
    const float x6  = __ldg(xr + 63u + u);
    const float x7a = __ldg(xr + 127u + u2);
    const float x7b = __ldg(xr + 128u + u2);

    // ---- top path prefix product, emitting top node probs ----
    float p = 1.0f;
#pragma unroll
    for (int d = 0; d < 6; ++d) {
        const unsigned node = ((1u << d) - 1u) + (u >> (6 - d));
        if ((u & ((1u << (6 - d)) - 1u)) == 0u) {
            on[node] = p;                    // path prob of node at depth d
        }
        p = ((u >> (5 - d)) & 1u) ? one_minus_mul(xt[d], p) : (p * xt[d]);
    }

    // ---- exclusively-owned nodes ----
    on[63u + u] = p;                         // depth 6
    const float p7a = p * x6;                // node 127+2u
    const float p7b = one_minus_mul(x6, p);  // node 128+2u
    on[127u + u2] = p7a;
    on[128u + u2] = p7b;

    // ---- leaves 4u..4u+3 (aligned float4 store) ----
    float4 leaf;
    leaf.x = p7a * x7a;
    leaf.y = one_minus_mul(x7a, p7a);
    leaf.z = p7b * x7b;
    leaf.w = one_minus_mul(x7b, p7b);
    *reinterpret_cast<float4*>(out + b * 256u + 4u * u) = leaf;
}

extern "C" void kernel_launch(void* const* d_in, const int* in_sizes, int n_in,
                              void* d_out, int out_size) {
    const float* x = (const float*)d_in[0];  // (BATCH, 255) float32
    float* out = (float*)d_out;
    const int batch = in_sizes[0] / 255;     // 512
    tree_path_kernel<<<batch, 64>>>(x, out, batch);
}

// round 9
// speedup vs baseline: 1.4726x; 1.4247x over previous
#include <cuda_runtime.h>

// Soft decision tree path probabilities — barrier-free, smem-free.
// Compile-time shapes: DEPTH=8, N_NODES=255, N_LEAVES=256, BATCH=512.
// Best-measured config: one row per 64-thread CTA, grid=512 (ncu 4.32us).
//
// Thread u owns the depth-6 subtree over leaves 4u..4u+3. Its 9 x-loads are
// index-computable and issued together (top-path loads are warp-broadcast
// from ~2 cache lines):
//   top path d=0..5 : node = (2^d-1) + (u >> (6-d))
//   depth-6         : 63 + u
//   depth-7         : 127+2u, 128+2u
// Prefix product before the depth-d factor IS node_d's path prob: top nodes
// written by the leftmost thread of each subtree; deeper nodes written
// unconditionally by their owner. Child 2i+1 takes factor x[i], child 2i+2
// takes 1-x[i]; (1-x)*p contracted to fmaf(-x,p,p) (1 FFMA, ~1ulp delta).
//
// Output: [ leaf_probs (512 x 256) ; node_probs (512 x 255) ] row-major.

#define BATCH    512
#define NODE_OFF (BATCH * 256)   // 131072, start of node-prob block

__device__ __forceinline__ float one_minus_mul(float xv, float p) {
    return fmaf(-xv, p, p);      // (1 - xv) * p
}

__global__ __launch_bounds__(64) void tree_path_kernel(
    const float* __restrict__ x,   // (512, 255)
    float* __restrict__ out)
{
    const unsigned u  = threadIdx.x;       // 0..63
    const unsigned b  = blockIdx.x;        // 0..511
    const unsigned u2 = u + u;

    const float* __restrict__ xr = x + b * 255u;
    float* __restrict__ on = out + NODE_OFF + b * 255u;

    // ---- issue all 9 independent loads up front ----
    float xt[6];
#pragma unroll
    for (int d = 0; d < 6; ++d) {
        const unsigned node = ((1u << d) - 1u) + (u >> (6 - d));
        xt[d] = __ldg(xr + node);
    }
    const float x6  = __ldg(xr + 63u + u);
    const float x7a = __ldg(xr + 127u + u2);
    const float x7b = __ldg(xr + 128u + u2);

    // ---- top path prefix product, emitting top node probs ----
    float p = 1.0f;
#pragma unroll
    for (int d = 0; d < 6; ++d) {
        const unsigned node = ((1u << d) - 1u) + (u >> (6 - d));
        if ((u & ((1u << (6 - d)) - 1u)) == 0u) {
            on[node] = p;                    // path prob of node at depth d
        }
        p = ((u >> (5 - d)) & 1u) ? one_minus_mul(xt[d], p) : (p * xt[d]);
    }

    // ---- exclusively-owned nodes ----
    on[63u + u] = p;                         // depth 6
    const float p7a = p * x6;                // node 127+2u
    const float p7b = one_minus_mul(x6, p);  // node 128+2u
    on[127u + u2] = p7a;
    on[128u + u2] = p7b;

    // ---- leaves 4u..4u+3 (aligned float4 store) ----
    float4 leaf;
    leaf.x = p7a * x7a;
    leaf.y = one_minus_mul(x7a, p7a);
    leaf.z = p7b * x7b;
    leaf.w = one_minus_mul(x7b, p7b);
    *reinterpret_cast<float4*>(out + (b << 8) + (u2 + u2)) = leaf;
}

extern "C" void kernel_launch(void* const* d_in, const int* in_sizes, int n_in,
                              void* d_out, int out_size) {
    const float* x = (const float*)d_in[0];  // (512, 255) float32
    float* out = (float*)d_out;
    tree_path_kernel<<<BATCH, 64>>>(x, out);
}